// round 15
// baseline (speedup 1.0000x reference)
#include <cuda_runtime.h>
#include <cuda_fp16.h>
#include <math.h>
#include <stdint.h>

#define BATCH   131072
#define HID     512
#define LDIM    8
#define NTH     45
#define NSTEPS  20

// ============================================================================
// Baseline-PTX tensor helpers (compute_103-safe: ldmatrix + mma.sync only)
// ============================================================================
__device__ __forceinline__ uint32_t smem_u32(const void* p) {
    uint32_t a;
    asm("{ .reg .u64 t; cvta.to.shared.u64 t, %1; cvt.u32.u64 %0, t; }"
        : "=r"(a) : "l"(p));
    return a;
}

#define LDSM4(r0, r1, r2, r3, addr) \
    asm volatile("ldmatrix.sync.aligned.m8n8.x4.shared.b16 {%0,%1,%2,%3}, [%4];" \
        : "=r"(r0), "=r"(r1), "=r"(r2), "=r"(r3) : "r"(addr))

#define LDSM2(r0, r1, addr) \
    asm volatile("ldmatrix.sync.aligned.m8n8.x2.shared.b16 {%0,%1}, [%2];" \
        : "=r"(r0), "=r"(r1) : "r"(addr))

// fp16 inputs, fp32 accumulate
#define MMA16816(d, a, b0, b1) \
    asm volatile("mma.sync.aligned.m16n8k16.row.col.f32.f16.f16.f32 " \
        "{%0,%1,%2,%3},{%4,%5,%6,%7},{%8,%9},{%0,%1,%2,%3};" \
        : "+f"((d)[0]), "+f"((d)[1]), "+f"((d)[2]), "+f"((d)[3]) \
        : "r"((a)[0]), "r"((a)[1]), "r"((a)[2]), "r"((a)[3]), \
          "r"(b0), "r"(b1))

__device__ __forceinline__ void cp16(uint32_t dst, const void* src) {
    asm volatile("cp.async.cg.shared.global [%0], [%1], 16;"
        :: "r"(dst), "l"(src));
}
#define CP_COMMIT() asm volatile("cp.async.commit_group;" ::: "memory")
#define CP_WAIT(n)  asm volatile("cp.async.wait_group %0;" :: "n"(n) : "memory")

__device__ __forceinline__ uint32_t pack_h2(float a, float b) {
    __half2 t = __floats2half2_rn(a, b);
    return reinterpret_cast<uint32_t&>(t);
}

// ============================================================================
// Scratch
// ============================================================================
__device__ __half g_hA[BATCH * HID];      // integrate+dec1 output
__device__ float  g_z0[BATCH * LDIM];

__device__ __half g_w1[512 * 64];     // enc_W1  KPAD=64  (WT[n][k])
__device__ __half g_w2[512 * 512];    // enc_W2  KPAD=512
__device__ __half g_d2[512 * 512];    // dec_W2  KPAD=512
__device__ __half g_d3[64 * 512];     // dec_W3  KPAD=512

// ============================================================================
// prep: weights in ONE launch (transpose + fp16 round + zero-pad)
// ============================================================================
#define SEG0 32768            // w1  (K=64,  N=512, KPAD=64)
#define SEG1 (SEG0 + 262144)  // w2  (K=512, N=512, KPAD=512)
#define SEG2 (SEG1 + 262144)  // d2  (K=512, N=512, KPAD=512)
#define SEG3 (SEG2 + 32768)   // d3  (K=512, N=64,  KPAD=512)

__global__ void prep_all_kernel(const float* __restrict__ eW1,
                                const float* __restrict__ eW2,
                                const float* __restrict__ dW2,
                                const float* __restrict__ dW3,
                                __half* __restrict__ w1, __half* __restrict__ w2,
                                __half* __restrict__ d2, __half* __restrict__ d3)
{
    int idx = blockIdx.x * 256 + threadIdx.x;
    if (idx >= SEG3) return;
    const float* W; __half* O; int K, N, KPAD, off;
    if (idx < SEG0)      { W = eW1; O = w1; K = 64;  N = 512; KPAD = 64;  off = 0;    }
    else if (idx < SEG1) { W = eW2; O = w2; K = 512; N = 512; KPAD = 512; off = SEG0; }
    else if (idx < SEG2) { W = dW2; O = d2; K = 512; N = 512; KPAD = 512; off = SEG1; }
    else                 { W = dW3; O = d3; K = 512; N = 64;  KPAD = 512; off = SEG2; }
    int i = idx - off;
    int n = i / KPAD, k = i % KPAD;
    float v = (k < K) ? W[(size_t)k * N + n] : 0.f;
    O[i] = __float2half_rn(v);
}

// ============================================================================
// ENC fused kernel: z0 = tanh( enc3( SiLU(LN( SiLU(LN(x@W1+b1))@W2+b2 )) ) )
// CTA: 64 rows, 256 thr = 8 warps, warp tile m64 x n64 (proven mainloop).
// Phase A: K=64 GEMM (x@W1) -> LN/SiLU -> resident smem A (chunk w == warp w).
// Phase B: K=512 GEMM reading A from resident smem, W2 double-buffered.
// Smem: ARES 73728 | WST0 73728 | WST1 73728 | PAR 6144 | RED 1024 | SZ 2048
//       phase A: x tile at WST1[0:9216), enc1 params at WST1+9216 (6144)
//       W3 staged into WST0 after the mainloop (dead).
// ============================================================================
#define LDR 144
#define E_ARES   0
#define E_WST(s) (73728 + (s) * 73728)
#define E_PAR    221184
#define E_RED    227328
#define E_SZ     228352
#define SM_ENC   230400

__global__ __launch_bounds__(256, 1)
void enc_fused_kernel(const float* __restrict__ x0,
                      const __half* __restrict__ W1g,
                      const float* __restrict__ b1, const float* __restrict__ g1,
                      const float* __restrict__ be1,
                      const __half* __restrict__ W2g,
                      const float* __restrict__ b2, const float* __restrict__ g2,
                      const float* __restrict__ be2,
                      const float* __restrict__ W3, const float* __restrict__ b3,
                      float* __restrict__ z0out)
{
    extern __shared__ char smem[];
    const uint32_t sb = smem_u32(smem);
    const int tid = threadIdx.x, lane = tid & 31, w = tid >> 5;  // 8 warps
    const int nbase = w * 64;
    const int tile = blockIdx.x;

    float* sB2  = (float*)(smem + E_PAR);
    float* sG2  = (float*)(smem + E_PAR + 2048);
    float* sBe2 = (float*)(smem + E_PAR + 4096);
    float* sSum  = (float*)(smem + E_RED);
    float* sSum2 = (float*)(smem + E_RED + 256);
    float* sMu   = (float*)(smem + E_RED + 512);
    float* sRs   = (float*)(smem + E_RED + 768);
    float* sZ    = (float*)(smem + E_SZ);
    // phase A params live in WST1 + 9216
    float* sB1  = (float*)(smem + E_WST(1) + 9216);
    float* sG1  = sB1 + 512;
    float* sBe1 = sB1 + 1024;

    for (int i = tid; i < 512; i += 256) {
        sB2[i] = b2[i]; sG2[i] = g2[i]; sBe2[i] = be2[i];
        sB1[i] = b1[i]; sG1[i] = g1[i]; sBe1[i] = be1[i];
        sZ[i]  = 0.f;
    }
    if (tid < 64) { sSum[tid] = 0.f; sSum2[tid] = 0.f; }

    // x tile: 64 rows x 64 fp32 -> fp16 staged at WST1 base (pitch 144)
    for (int i = tid; i < 1024; i += 256) {
        const int row = i >> 4, q = i & 15;             // 16 float4 per row
        float4 v = *(const float4*)(x0 + ((size_t)tile * 64 + row) * 64 + q * 4);
        uint32_t* dst = (uint32_t*)(smem + E_WST(1) + row * LDR + q * 8);
        dst[0] = pack_h2(v.x, v.y);
        dst[1] = pack_h2(v.z, v.w);
    }
    // W1 (512 rows x 64 cols fp16) -> WST0
    for (int i = tid; i < 4096; i += 256) {
        const int row = i >> 3, j = i & 7;
        cp16(sb + E_WST(0) + row * LDR + j * 16,
             (const char*)W1g + ((size_t)row * 64) * 2 + j * 16);
    }
    CP_COMMIT();

    const int arow = ((lane >> 3) & 1) * 8 + (lane & 7);
    const int acol = (lane >> 4) * 8;
    const int brow = ((lane >> 4) & 1) * 8 + (lane & 7);
    const int bcol = ((lane >> 3) & 1) * 8;

    float acc[4][8][4];
#pragma unroll
    for (int i = 0; i < 4; i++)
#pragma unroll
        for (int j = 0; j < 8; j++)
#pragma unroll
            for (int r = 0; r < 4; r++) acc[i][j][r] = 0.f;

    CP_WAIT(0);
    __syncthreads();

    // -------- phase A mainloop: one K=64 chunk: A=x (WST1), B=W1 (WST0) -----
    {
        const uint32_t bA = sb + E_WST(1);
        const uint32_t bB = sb + E_WST(0);
#pragma unroll
        for (int ks = 0; ks < 64; ks += 16) {
            uint32_t ah[4][4];
#pragma unroll
            for (int mf = 0; mf < 4; mf++) {
                const uint32_t ao = (uint32_t)((mf * 16 + arow) * LDR + (ks + acol) * 2);
                LDSM4(ah[mf][0], ah[mf][1], ah[mf][2], ah[mf][3], bA + ao);
            }
#pragma unroll
            for (int nq = 0; nq < 4; nq++) {
                const uint32_t bo = (uint32_t)((nbase + nq * 16 + brow) * LDR
                                               + (ks + bcol) * 2);
                uint32_t b[4];
                LDSM4(b[0], b[1], b[2], b[3], bB + bo);
#pragma unroll
                for (int mf = 0; mf < 4; mf++) {
                    MMA16816(acc[mf][nq * 2],     ah[mf], b[0], b[1]);
                    MMA16816(acc[mf][nq * 2 + 1], ah[mf], b[2], b[3]);
                }
            }
        }
    }

    // -------- phase A epilogue: bias1 + LN + SiLU -> resident A chunk w -----
#pragma unroll
    for (int mf = 0; mf < 4; mf++)
#pragma unroll
        for (int rh = 0; rh < 2; rh++) {
            float s = 0.f, s2 = 0.f;
#pragma unroll
            for (int idx = 0; idx < 8; idx++) {
                const int c0 = nbase + idx * 8 + (lane & 3) * 2;
                float v0 = acc[mf][idx][rh * 2]     + sB1[c0];
                float v1 = acc[mf][idx][rh * 2 + 1] + sB1[c0 + 1];
                acc[mf][idx][rh * 2] = v0; acc[mf][idx][rh * 2 + 1] = v1;
                s += v0 + v1; s2 += v0 * v0 + v1 * v1;
            }
            s  += __shfl_xor_sync(0xffffffffu, s, 1);
            s  += __shfl_xor_sync(0xffffffffu, s, 2);
            s2 += __shfl_xor_sync(0xffffffffu, s2, 1);
            s2 += __shfl_xor_sync(0xffffffffu, s2, 2);
            if ((lane & 3) == 0) {
                const int row = mf * 16 + (lane >> 2) + rh * 8;
                atomicAdd(&sSum[row], s);
                atomicAdd(&sSum2[row], s2);
            }
        }
    __syncthreads();
    if (tid < 64) {
        const float mu = sSum[tid] * (1.f / 512.f);
        const float var = sSum2[tid] * (1.f / 512.f) - mu * mu;
        sMu[tid] = mu; sRs[tid] = rsqrtf(var + 1e-5f);
    }
    __syncthreads();

#pragma unroll
    for (int mf = 0; mf < 4; mf++)
#pragma unroll
        for (int rh = 0; rh < 2; rh++) {
            const int row = mf * 16 + (lane >> 2) + rh * 8;
            const float mu = sMu[row], rs = sRs[row];
#pragma unroll
            for (int idx = 0; idx < 8; idx++) {
                const int cl = idx * 8 + (lane & 3) * 2;   // local col in chunk w
                const int c0 = nbase + cl;
                float y0 = (acc[mf][idx][rh * 2]     - mu) * rs * sG1[c0]     + sBe1[c0];
                float y1 = (acc[mf][idx][rh * 2 + 1] - mu) * rs * sG1[c0 + 1] + sBe1[c0 + 1];
                y0 = y0 * (1.f / (1.f + __expf(-y0)));
                y1 = y1 * (1.f / (1.f + __expf(-y1)));
                *(uint32_t*)(smem + E_ARES + w * 9216 + row * LDR + cl * 2)
                    = pack_h2(y0, y1);
            }
        }
    __syncthreads();    // params/stage reads done; ARES visible

    // re-zero reduction for phase B
    if (tid < 64) { sSum[tid] = 0.f; sSum2[tid] = 0.f; }

    // -------- phase B: K=512 GEMM, A resident, W2 double-buffered ----------
    auto loadW = [&](int c, int s) {
        const int kbase = c * 64;
        const uint32_t bB = sb + E_WST(s);
#pragma unroll
        for (int i = tid; i < 4096; i += 256) {
            const int row = i >> 3, j = i & 7;
            cp16(bB + row * LDR + j * 16,
                 (const char*)W2g + ((size_t)row * 512 + kbase) * 2 + j * 16);
        }
        CP_COMMIT();
    };
    loadW(0, 0);
    loadW(1, 1);

#pragma unroll
    for (int i = 0; i < 4; i++)
#pragma unroll
        for (int j = 0; j < 8; j++)
#pragma unroll
            for (int r = 0; r < 4; r++) acc[i][j][r] = 0.f;

#pragma unroll 1
    for (int c = 0; c < 8; c++) {
        if (c + 1 < 8) CP_WAIT(1); else CP_WAIT(0);
        __syncthreads();
        const int sel = c & 1;
        const uint32_t bA = sb + E_ARES + c * 9216;
        const uint32_t bB = sb + E_WST(sel);
#pragma unroll
        for (int ks = 0; ks < 64; ks += 16) {
            uint32_t ah[4][4];
#pragma unroll
            for (int mf = 0; mf < 4; mf++) {
                const uint32_t ao = (uint32_t)((mf * 16 + arow) * LDR + (ks + acol) * 2);
                LDSM4(ah[mf][0], ah[mf][1], ah[mf][2], ah[mf][3], bA + ao);
            }
#pragma unroll
            for (int nq = 0; nq < 4; nq++) {
                const uint32_t bo = (uint32_t)((nbase + nq * 16 + brow) * LDR
                                               + (ks + bcol) * 2);
                uint32_t b[4];
                LDSM4(b[0], b[1], b[2], b[3], bB + bo);
#pragma unroll
                for (int mf = 0; mf < 4; mf++) {
                    MMA16816(acc[mf][nq * 2],     ah[mf], b[0], b[1]);
                    MMA16816(acc[mf][nq * 2 + 1], ah[mf], b[2], b[3]);
                }
            }
        }
        __syncthreads();
        if (c + 2 < 8) loadW(c + 2, sel);
    }

    // -------- phase B epilogue: bias2 + LN stats -----------------------------
#pragma unroll
    for (int mf = 0; mf < 4; mf++)
#pragma unroll
        for (int rh = 0; rh < 2; rh++) {
            float s = 0.f, s2 = 0.f;
#pragma unroll
            for (int idx = 0; idx < 8; idx++) {
                const int c0 = nbase + idx * 8 + (lane & 3) * 2;
                float v0 = acc[mf][idx][rh * 2]     + sB2[c0];
                float v1 = acc[mf][idx][rh * 2 + 1] + sB2[c0 + 1];
                acc[mf][idx][rh * 2] = v0; acc[mf][idx][rh * 2 + 1] = v1;
                s += v0 + v1; s2 += v0 * v0 + v1 * v1;
            }
            s  += __shfl_xor_sync(0xffffffffu, s, 1);
            s  += __shfl_xor_sync(0xffffffffu, s, 2);
            s2 += __shfl_xor_sync(0xffffffffu, s2, 1);
            s2 += __shfl_xor_sync(0xffffffffu, s2, 2);
            if ((lane & 3) == 0) {
                const int row = mf * 16 + (lane >> 2) + rh * 8;
                atomicAdd(&sSum[row], s);
                atomicAdd(&sSum2[row], s2);
            }
        }
    // stage W3 into dead WST0 while stats settle
    float* sW3 = (float*)(smem + E_WST(0));
    for (int i = tid; i < 512 * 8; i += 256) sW3[i] = W3[i];
    __syncthreads();
    if (tid < 64) {
        const float mu = sSum[tid] * (1.f / 512.f);
        const float var = sSum2[tid] * (1.f / 512.f) - mu * mu;
        sMu[tid] = mu; sRs[tid] = rsqrtf(var + 1e-5f);
    }
    __syncthreads();

    // -------- LN + SiLU + fused enc3: z = tanh(h @ W3 + b3) -----------------
#pragma unroll
    for (int mf = 0; mf < 4; mf++)
#pragma unroll
        for (int rh = 0; rh < 2; rh++) {
            const int row = mf * 16 + (lane >> 2) + rh * 8;
            const float mu = sMu[row], rs = sRs[row];
            float zp[8];
#pragma unroll
            for (int j = 0; j < 8; j++) zp[j] = 0.f;
#pragma unroll
            for (int idx = 0; idx < 8; idx++) {
                const int c0 = nbase + idx * 8 + (lane & 3) * 2;
                float y0 = (acc[mf][idx][rh * 2]     - mu) * rs * sG2[c0]     + sBe2[c0];
                float y1 = (acc[mf][idx][rh * 2 + 1] - mu) * rs * sG2[c0 + 1] + sBe2[c0 + 1];
                y0 = y0 * (1.f / (1.f + __expf(-y0)));
                y1 = y1 * (1.f / (1.f + __expf(-y1)));
                const float* w0 = sW3 + c0 * 8;
#pragma unroll
                for (int j = 0; j < 8; j++) {
                    zp[j] = fmaf(y0, w0[j], zp[j]);
                    zp[j] = fmaf(y1, w0[8 + j], zp[j]);
                }
            }
#pragma unroll
            for (int j = 0; j < 8; j++) {
                zp[j] += __shfl_xor_sync(0xffffffffu, zp[j], 1);
                zp[j] += __shfl_xor_sync(0xffffffffu, zp[j], 2);
            }
            if ((lane & 3) == 0)
#pragma unroll
                for (int j = 0; j < 8; j++)
                    atomicAdd(&sZ[row * 8 + j], zp[j]);
        }
    __syncthreads();
    if (tid < 64) {
        const size_t rowg = (size_t)tile * 64 + tid;
#pragma unroll
        for (int j = 0; j < 8; j++)
            z0out[rowg * 8 + j] = tanhf(sZ[tid * 8 + j] + __ldg(b3 + j));
    }
}

// ============================================================================
// DEC fused kernel: out = (SiLU(LN(A@W2+b2))) @ W3 + b3
// Standard k512 mainloop (A = g_hA from integrator, W2 double-buffered),
// epilogue writes h2 into dead stage-0 smem (chunk w == warp w), W3 loaded
// into dead stage-1 overlapping the epilogue, then an n8-per-warp MMA pass.
// Smem: stage(s) = s*82944 [A 9216 | B 73728], PAR 165888, RED 172032.
// ============================================================================
#define D_ST(s)  ((s) * 82944)
#define D_PAR    165888
#define D_RED    172032
#define SM_DEC   173056

__global__ __launch_bounds__(256, 1)
void dec_fused_kernel(const __half* __restrict__ A,
                      const __half* __restrict__ Wg,
                      const float* __restrict__ b2, const float* __restrict__ g2,
                      const float* __restrict__ be2,
                      const __half* __restrict__ W3h,
                      const float* __restrict__ b3,
                      float* __restrict__ out)
{
    extern __shared__ char smem[];
    const uint32_t sb = smem_u32(smem);
    const int tid = threadIdx.x, lane = tid & 31, w = tid >> 5;
    const int nbase = w * 64;
    const int tile = blockIdx.x;

    float* sB2  = (float*)(smem + D_PAR);
    float* sG2  = (float*)(smem + D_PAR + 2048);
    float* sBe2 = (float*)(smem + D_PAR + 4096);
    float* sSum  = (float*)(smem + D_RED);
    float* sSum2 = (float*)(smem + D_RED + 256);
    float* sMu   = (float*)(smem + D_RED + 512);
    float* sRs   = (float*)(smem + D_RED + 768);

    for (int i = tid; i < 512; i += 256) { sB2[i] = b2[i]; sG2[i] = g2[i]; sBe2[i] = be2[i]; }
    if (tid < 64) { sSum[tid] = 0.f; sSum2[tid] = 0.f; }

    auto load_chunk = [&](int c, int s) {
        const int kbase = c * 64;
        const uint32_t bB = sb + D_ST(s) + 9216;
#pragma unroll
        for (int i = tid; i < 4096; i += 256) {
            const int row = i >> 3, j = i & 7;
            cp16(bB + row * LDR + j * 16,
                 (const char*)Wg + ((size_t)row * 512 + kbase) * 2 + j * 16);
        }
#pragma unroll
        for (int i = tid; i < 512; i += 256) {
            const int row = i >> 3, j = i & 7;
            cp16(sb + D_ST(s) + row * LDR + j * 16,
                 (const char*)A + (((size_t)tile * 64 + row) * 512 + kbase) * 2 + j * 16);
        }
        CP_COMMIT();
    };
    load_chunk(0, 0);
    load_chunk(1, 1);

    float acc[4][8][4];
#pragma unroll
    for (int i = 0; i < 4; i++)
#pragma unroll
        for (int j = 0; j < 8; j++)
#pragma unroll
            for (int r = 0; r < 4; r++) acc[i][j][r] = 0.f;

    const int arow = ((lane >> 3) & 1) * 8 + (lane & 7);
    const int acol = (lane >> 4) * 8;
    const int brow = ((lane >> 4) & 1) * 8 + (lane & 7);
    const int bcol = ((lane >> 3) & 1) * 8;

#pragma unroll 1
    for (int c = 0; c < 8; c++) {
        if (c + 1 < 8) CP_WAIT(1); else CP_WAIT(0);
        __syncthreads();
        const int sel = c & 1;
        const uint32_t bA = sb + D_ST(sel);
        const uint32_t bB = sb + D_ST(sel) + 9216;
#pragma unroll
        for (int ks = 0; ks < 64; ks += 16) {
            uint32_t ah[4][4];
#pragma unroll
            for (int mf = 0; mf < 4; mf++) {
                const uint32_t ao = (uint32_t)((mf * 16 + arow) * LDR + (ks + acol) * 2);
                LDSM4(ah[mf][0], ah[mf][1], ah[mf][2], ah[mf][3], bA + ao);
            }
#pragma unroll
            for (int nq = 0; nq < 4; nq++) {
                const uint32_t bo = (uint32_t)((nbase + nq * 16 + brow) * LDR
                                               + (ks + bcol) * 2);
                uint32_t b[4];
                LDSM4(b[0], b[1], b[2], b[3], bB + bo);
#pragma unroll
                for (int mf = 0; mf < 4; mf++) {
                    MMA16816(acc[mf][nq * 2],     ah[mf], b[0], b[1]);
                    MMA16816(acc[mf][nq * 2 + 1], ah[mf], b[2], b[3]);
                }
            }
        }
        __syncthreads();
        if (c + 2 < 8) load_chunk(c + 2, sel);
    }

    // -------- epilogue: bias2 + LN stats; W3 -> stage1 (dead) overlapped ----
#pragma unroll
    for (int mf = 0; mf < 4; mf++)
#pragma unroll
        for (int rh = 0; rh < 2; rh++) {
            float s = 0.f, s2 = 0.f;
#pragma unroll
            for (int idx = 0; idx < 8; idx++) {
                const int c0 = nbase + idx * 8 + (lane & 3) * 2;
                float v0 = acc[mf][idx][rh * 2]     + sB2[c0];
                float v1 = acc[mf][idx][rh * 2 + 1] + sB2[c0 + 1];
                acc[mf][idx][rh * 2] = v0; acc[mf][idx][rh * 2 + 1] = v1;
                s += v0 + v1; s2 += v0 * v0 + v1 * v1;
            }
            s  += __shfl_xor_sync(0xffffffffu, s, 1);
            s  += __shfl_xor_sync(0xffffffffu, s, 2);
            s2 += __shfl_xor_sync(0xffffffffu, s2, 1);
            s2 += __shfl_xor_sync(0xffffffffu, s2, 2);
            if ((lane & 3) == 0) {
                const int row = mf * 16 + (lane >> 2) + rh * 8;
                atomicAdd(&sSum[row], s);
                atomicAdd(&sSum2[row], s2);
            }
        }
    // W3 chunks -> stage1 region (all mainloop reads finished)
    {
        const uint32_t s1 = sb + D_ST(1);
#pragma unroll
        for (int i = tid; i < 4096; i += 256) {
            const int ck = i >> 9, rem = i & 511;
            const int row = rem >> 3, j = rem & 7;
            cp16(s1 + ck * 9216 + row * LDR + j * 16,
                 (const char*)W3h + ((size_t)row * 512 + ck * 64) * 2 + j * 16);
        }
        CP_COMMIT();
    }
    __syncthreads();
    if (tid < 64) {
        const float mu = sSum[tid] * (1.f / 512.f);
        const float var = sSum2[tid] * (1.f / 512.f) - mu * mu;
        sMu[tid] = mu; sRs[tid] = rsqrtf(var + 1e-5f);
    }
    __syncthreads();

    // -------- LN + SiLU -> h2 into stage0 (chunk w) --------------------------
#pragma unroll
    for (int mf = 0; mf < 4; mf++)
#pragma unroll
        for (int rh = 0; rh < 2; rh++) {
            const int row = mf * 16 + (lane >> 2) + rh * 8;
            const float mu = sMu[row], rs = sRs[row];
#pragma unroll
            for (int idx = 0; idx < 8; idx++) {
                const int cl = idx * 8 + (lane & 3) * 2;
                const int c0 = nbase + cl;
                float y0 = (acc[mf][idx][rh * 2]     - mu) * rs * sG2[c0]     + sBe2[c0];
                float y1 = (acc[mf][idx][rh * 2 + 1] - mu) * rs * sG2[c0 + 1] + sBe2[c0 + 1];
                y0 = y0 * (1.f / (1.f + __expf(-y0)));
                y1 = y1 * (1.f / (1.f + __expf(-y1)));
                *(uint32_t*)(smem + D_ST(0) + w * 9216 + row * LDR + cl * 2)
                    = pack_h2(y0, y1);
            }
        }
    CP_WAIT(0);
    __syncthreads();

    // -------- out phase: out[64,64] = h2 @ W3^T; warp w owns n8 cols ---------
    float acc2[4][4];
#pragma unroll
    for (int i = 0; i < 4; i++)
#pragma unroll
        for (int r = 0; r < 4; r++) acc2[i][r] = 0.f;

    const int l16 = lane & 15;
#pragma unroll 1
    for (int ck = 0; ck < 8; ck++) {
        const uint32_t bA = sb + D_ST(0) + ck * 9216;
        const uint32_t s1 = sb + D_ST(1) + ck * 9216;
#pragma unroll
        for (int ks = 0; ks < 64; ks += 16) {
            uint32_t ah[4][4];
#pragma unroll
            for (int mf = 0; mf < 4; mf++) {
                const uint32_t ao = (uint32_t)((mf * 16 + arow) * LDR + (ks + acol) * 2);
                LDSM4(ah[mf][0], ah[mf][1], ah[mf][2], ah[mf][3], bA + ao);
            }
            uint32_t b0, b1;
            const uint32_t bo = (uint32_t)((w * 8 + (l16 & 7)) * LDR + ks * 2
                                           + ((l16 >> 3) << 4));
            LDSM2(b0, b1, s1 + bo);
#pragma unroll
            for (int mf = 0; mf < 4; mf++)
                MMA16816(acc2[mf], ah[mf], b0, b1);
        }
    }

#pragma unroll
    for (int mf = 0; mf < 4; mf++)
#pragma unroll
        for (int rh = 0; rh < 2; rh++) {
            const int row = mf * 16 + (lane >> 2) + rh * 8;
            const int c0 = w * 8 + (lane & 3) * 2;
            float2 o;
            o.x = acc2[mf][rh * 2]     + __ldg(b3 + c0);
            o.y = acc2[mf][rh * 2 + 1] + __ldg(b3 + c0 + 1);
            *(float2*)(out + ((size_t)tile * 64 + row) * 64 + c0) = o;
        }
}

// ============================================================================
// integrator + FUSED dec layer 1 (unchanged from round 14)
// ============================================================================
__global__ __launch_bounds__(256, 2)
void integrate_dec1_kernel(const float* __restrict__ z0,
                           const float* __restrict__ dtv,
                           const float* __restrict__ Xi,
                           const float* __restrict__ W1,   // dec_W1 [8][512] fp32
                           const float* __restrict__ b1,
                           const float* __restrict__ g1,
                           const float* __restrict__ be1,
                           __half* __restrict__ O)
{
    __shared__ float Xis[NTH * LDIM];
    __shared__ float sW[8 * 512];
    __shared__ float sB1[512], sG1[512], sBe1[512];
    __shared__ float sZr[256 * 9];

    const int tid = threadIdx.x, lane = tid & 31, w = tid >> 5;
    for (int i = tid; i < NTH * LDIM; i += 256) Xis[i] = Xi[i];
    for (int i = tid; i < 8 * 512; i += 256) sW[i] = W1[i];
    for (int i = tid; i < 512; i += 256) { sB1[i] = b1[i]; sG1[i] = g1[i]; sBe1[i] = be1[i]; }
    __syncthreads();

    const size_t row = (size_t)blockIdx.x * 256 + tid;
    float z[8];
    *(float4*)&z[0] = *(const float4*)(z0 + row * 8);
    *(float4*)&z[4] = *(const float4*)(z0 + row * 8 + 4);
    const float dt = dtv[row] * (1.f / (float)NSTEPS);

#pragma unroll 1
    for (int s = 0; s < NSTEPS; s++) {
        float zd[8];
#pragma unroll
        for (int j = 0; j < 8; j++) zd[j] = Xis[j];
#pragma unroll
        for (int i = 0; i < 8; i++) {
            const float t = z[i];
#pragma unroll
            for (int j = 0; j < 8; j++)
                zd[j] = fmaf(t, Xis[(1 + i) * 8 + j], zd[j]);
        }
        int idx = 9;
#pragma unroll
        for (int i = 0; i < 8; i++)
#pragma unroll
            for (int k = i; k < 8; k++) {
                const float q = z[i] * z[k];
#pragma unroll
                for (int j = 0; j < 8; j++)
                    zd[j] = fmaf(q, Xis[idx * 8 + j], zd[j]);
                idx++;
            }
#pragma unroll
        for (int j = 0; j < 8; j++) z[j] = fmaf(zd[j], dt, z[j]);
    }
#pragma unroll
    for (int j = 0; j < 8; j++) sZr[tid * 9 + j] = z[j];
    __syncthreads();

    const size_t rowbase = (size_t)blockIdx.x * 256;
#pragma unroll 1
    for (int it = 0; it < 32; it++) {
        const int lr = it * 8 + w;
        float zz[8];
#pragma unroll
        for (int k = 0; k < 8; k++) zz[k] = sZr[lr * 9 + k];
        float a0[8], a1[8];
#pragma unroll
        for (int j = 0; j < 8; j++) {
            const int c0 = j * 64 + lane * 2;
            float x0 = sB1[c0], x1 = sB1[c0 + 1];
#pragma unroll
            for (int k = 0; k < 8; k++) {
                x0 = fmaf(zz[k], sW[k * 512 + c0],     x0);
                x1 = fmaf(zz[k], sW[k * 512 + c0 + 1], x1);
            }
            a0[j] = x0; a1[j] = x1;
        }
        float s = 0.f, s2 = 0.f;
#pragma unroll
        for (int j = 0; j < 8; j++) {
            s += a0[j] + a1[j]; s2 += a0[j] * a0[j] + a1[j] * a1[j];
        }
#pragma unroll
        for (int o = 16; o; o >>= 1) {
            s  += __shfl_xor_sync(0xffffffffu, s, o);
            s2 += __shfl_xor_sync(0xffffffffu, s2, o);
        }
        const float mu = s * (1.f / 512.f);
        const float rs = rsqrtf(s2 * (1.f / 512.f) - mu * mu + 1e-5f);
        __half* orow = O + (rowbase + lr) * 512;
#pragma unroll
        for (int j = 0; j < 8; j++) {
            const int c0 = j * 64 + lane * 2;
            float y0 = (a0[j] - mu) * rs * sG1[c0]     + sBe1[c0];
            float y1 = (a1[j] - mu) * rs * sG1[c0 + 1] + sBe1[c0 + 1];
            y0 = y0 * (1.f / (1.f + __expf(-y0)));
            y1 = y1 * (1.f / (1.f + __expf(-y1)));
            *(uint32_t*)(orow + c0) = pack_h2(y0, y1);
        }
    }
}

// ============================================================================
extern "C" void kernel_launch(void* const* d_in, const int* in_sizes, int n_in,
                              void* d_out, int out_size)
{
    (void)in_sizes; (void)n_in; (void)out_size;
    const float* x0   = (const float*)d_in[0];
    const float* dtn  = (const float*)d_in[1];
    const float* eW1  = (const float*)d_in[4];
    const float* eb1  = (const float*)d_in[5];
    const float* eg1  = (const float*)d_in[6];
    const float* ebe1 = (const float*)d_in[7];
    const float* eW2  = (const float*)d_in[8];
    const float* eb2  = (const float*)d_in[9];
    const float* eg2  = (const float*)d_in[10];
    const float* ebe2 = (const float*)d_in[11];
    const float* eW3  = (const float*)d_in[12];
    const float* eb3  = (const float*)d_in[13];
    const float* dW1  = (const float*)d_in[14];
    const float* db1  = (const float*)d_in[15];
    const float* dg1  = (const float*)d_in[16];
    const float* dbe1 = (const float*)d_in[17];
    const float* dW2  = (const float*)d_in[18];
    const float* db2  = (const float*)d_in[19];
    const float* dg2  = (const float*)d_in[20];
    const float* dbe2 = (const float*)d_in[21];
    const float* dW3  = (const float*)d_in[22];
    const float* db3  = (const float*)d_in[23];
    const float* Xi   = (const float*)d_in[24];
    float* out = (float*)d_out;

    __half *hA, *w1, *w2, *d2, *d3;
    float* z0;
    cudaGetSymbolAddress((void**)&hA, g_hA);
    cudaGetSymbolAddress((void**)&z0, g_z0);
    cudaGetSymbolAddress((void**)&w1, g_w1);
    cudaGetSymbolAddress((void**)&w2, g_w2);
    cudaGetSymbolAddress((void**)&d2, g_d2);
    cudaGetSymbolAddress((void**)&d3, g_d3);

    cudaFuncSetAttribute(enc_fused_kernel,
        cudaFuncAttributeMaxDynamicSharedMemorySize, SM_ENC);
    cudaFuncSetAttribute(dec_fused_kernel,
        cudaFuncAttributeMaxDynamicSharedMemorySize, SM_DEC);

    prep_all_kernel<<<(SEG3 + 255) / 256, 256>>>(eW1, eW2, dW2, dW3,
                                                 w1, w2, d2, d3);

    const int nwide = BATCH / 64;    // 2048

    // encoder (enc1 + enc2 + enc3 fused) -> z0
    enc_fused_kernel<<<nwide, 256, SM_ENC>>>(
        x0, w1, eb1, eg1, ebe1, w2, eb2, eg2, ebe2, eW3, eb3, z0);
    // integrator + dec1 -> hA
    integrate_dec1_kernel<<<BATCH / 256, 256>>>(z0, dtn, Xi, dW1, db1, dg1, dbe1, hA);
    // decoder (dec2 + dec3 fused) -> out
    dec_fused_kernel<<<nwide, 256, SM_DEC>>>(
        hA, d2, db2, dg2, dbe2, d3, db3, out);
}

// round 16
// speedup vs baseline: 1.0812x; 1.0812x over previous
#include <cuda_runtime.h>
#include <cuda_fp16.h>
#include <math.h>
#include <stdint.h>

#define BATCH   131072
#define HID     512
#define LDIM    8
#define NTH     45
#define NSTEPS  20

// ============================================================================
// Baseline-PTX tensor helpers (compute_103-safe: ldmatrix + mma.sync only)
// ============================================================================
__device__ __forceinline__ uint32_t smem_u32(const void* p) {
    uint32_t a;
    asm("{ .reg .u64 t; cvta.to.shared.u64 t, %1; cvt.u32.u64 %0, t; }"
        : "=r"(a) : "l"(p));
    return a;
}

#define LDSM4(r0, r1, r2, r3, addr) \
    asm volatile("ldmatrix.sync.aligned.m8n8.x4.shared.b16 {%0,%1,%2,%3}, [%4];" \
        : "=r"(r0), "=r"(r1), "=r"(r2), "=r"(r3) : "r"(addr))

#define LDSM2(r0, r1, addr) \
    asm volatile("ldmatrix.sync.aligned.m8n8.x2.shared.b16 {%0,%1}, [%2];" \
        : "=r"(r0), "=r"(r1) : "r"(addr))

// fp16 inputs, fp32 accumulate
#define MMA16816(d, a, b0, b1) \
    asm volatile("mma.sync.aligned.m16n8k16.row.col.f32.f16.f16.f32 " \
        "{%0,%1,%2,%3},{%4,%5,%6,%7},{%8,%9},{%0,%1,%2,%3};" \
        : "+f"((d)[0]), "+f"((d)[1]), "+f"((d)[2]), "+f"((d)[3]) \
        : "r"((a)[0]), "r"((a)[1]), "r"((a)[2]), "r"((a)[3]), \
          "r"(b0), "r"(b1))

__device__ __forceinline__ void cp16(uint32_t dst, const void* src) {
    asm volatile("cp.async.cg.shared.global [%0], [%1], 16;"
        :: "r"(dst), "l"(src));
}
#define CP_COMMIT() asm volatile("cp.async.commit_group;" ::: "memory")
#define CP_WAIT(n)  asm volatile("cp.async.wait_group %0;" :: "n"(n) : "memory")

__device__ __forceinline__ uint32_t pack_h2(float a, float b) {
    __half2 t = __floats2half2_rn(a, b);
    return reinterpret_cast<uint32_t&>(t);
}

// ============================================================================
// Scratch
// ============================================================================
__device__ __half g_hA[BATCH * HID];
__device__ __half g_x[BATCH * 64];
__device__ float  g_z0[BATCH * LDIM];

__device__ __half g_w1[512 * 64];     // enc_W1  KPAD=64
__device__ __half g_w2[512 * 512];    // enc_W2  KPAD=512
__device__ __half g_d2[512 * 512];    // dec_W2  KPAD=512
__device__ __half g_d3[64 * 512];     // dec_W3  KPAD=512

// ============================================================================
// prep: weights in ONE launch (transpose + fp16 round + zero-pad)
// ============================================================================
#define SEG0 32768            // w1  (K=64,  N=512, KPAD=64)
#define SEG1 (SEG0 + 262144)  // w2  (K=512, N=512, KPAD=512)
#define SEG2 (SEG1 + 262144)  // d2  (K=512, N=512, KPAD=512)
#define SEG3 (SEG2 + 32768)   // d3  (K=512, N=64,  KPAD=512)

__global__ void prep_all_kernel(const float* __restrict__ eW1,
                                const float* __restrict__ eW2,
                                const float* __restrict__ dW2,
                                const float* __restrict__ dW3,
                                __half* __restrict__ w1, __half* __restrict__ w2,
                                __half* __restrict__ d2, __half* __restrict__ d3)
{
    int idx = blockIdx.x * 256 + threadIdx.x;
    if (idx >= SEG3) return;
    const float* W; __half* O; int K, N, KPAD, off;
    if (idx < SEG0)      { W = eW1; O = w1; K = 64;  N = 512; KPAD = 64;  off = 0;    }
    else if (idx < SEG1) { W = eW2; O = w2; K = 512; N = 512; KPAD = 512; off = SEG0; }
    else if (idx < SEG2) { W = dW2; O = d2; K = 512; N = 512; KPAD = 512; off = SEG1; }
    else                 { W = dW3; O = d3; K = 512; N = 64;  KPAD = 512; off = SEG2; }
    int i = idx - off;
    int n = i / KPAD, k = i % KPAD;
    float v = (k < K) ? W[(size_t)k * N + n] : 0.f;
    O[i] = __float2half_rn(v);
}

__global__ void prep_x_kernel(const float* __restrict__ x0,
                              __half* __restrict__ xo)
{
    size_t idx = (size_t)blockIdx.x * 256 + threadIdx.x;
    xo[idx] = __float2half_rn(x0[idx]);
}

// ============================================================================
// Shared smem layout for wide kernels
// ============================================================================
#define LDR 144
#define WST      82944                          // bytes per stage
#define WS_A(s)  ((s) * WST)                    // A: 64*144  = 9216
#define WS_B(s)  ((s) * WST + 9216)             // B: 512*144 = 73728
#define WS_PAR   165888                         // bias/g/beta 3x2048
#define WS_RED   172032                         // sums/mu/rs 4x256
#define WS_Z     173056                         // 64x8 fp32 = 2048
#define WS_W3    175104                         // 512x8 fp32 = 16384
#define SM_WIDE  191488

// ============================================================================
// wide_mma_k512<WRITE_Z>: the proven 523us kernel (256 thr, m64n64, 255 regs)
// ============================================================================
template<bool WRITE_Z>
__global__ __launch_bounds__(256, 1)
void wide_mma_k512(const __half* __restrict__ A,
                   const __half* __restrict__ W,
                   const float* __restrict__ bias,
                   const float* __restrict__ gamma,
                   const float* __restrict__ beta,
                   __half* __restrict__ O,
                   const float* __restrict__ W3,
                   const float* __restrict__ b3,
                   float* __restrict__ z0out)
{
    constexpr int NC = 8;
    extern __shared__ char smem[];
    const uint32_t sb = smem_u32(smem);
    const int tid = threadIdx.x, lane = tid & 31, w = tid >> 5;
    const int nbase = w * 64;
    const int tile = blockIdx.x;

    float* sBias = (float*)(smem + WS_PAR);
    float* sG    = (float*)(smem + WS_PAR + 2048);
    float* sBe   = (float*)(smem + WS_PAR + 4096);
    float* sSum  = (float*)(smem + WS_RED);
    float* sSum2 = (float*)(smem + WS_RED + 256);
    float* sMu   = (float*)(smem + WS_RED + 512);
    float* sRs   = (float*)(smem + WS_RED + 768);
    float* sZ    = (float*)(smem + WS_Z);
    float* sW3   = (float*)(smem + WS_W3);

    for (int i = tid; i < 512; i += 256) {
        sBias[i] = bias[i]; sG[i] = gamma[i]; sBe[i] = beta[i];
    }
    if (tid < 64) { sSum[tid] = 0.f; sSum2[tid] = 0.f; }
    if (WRITE_Z) {
        for (int i = tid; i < 512; i += 256) sZ[i] = 0.f;
        for (int i = tid; i < 512 * 8; i += 256) sW3[i] = W3[i];
    }

    auto load_chunk = [&](int c, int sel) {
        const int kbase = c * 64;
        const uint32_t bB = sb + WS_B(sel);
#pragma unroll
        for (int i = tid; i < 4096; i += 256) {
            const int row = i >> 3, j = i & 7;
            cp16(bB + row * LDR + j * 16,
                 (const char*)W + ((size_t)row * 512 + kbase) * 2 + j * 16);
        }
#pragma unroll
        for (int i = tid; i < 512; i += 256) {
            const int row = i >> 3, j = i & 7;
            cp16(sb + WS_A(sel) + row * LDR + j * 16,
                 (const char*)A + (((size_t)tile * 64 + row) * 512 + kbase) * 2 + j * 16);
        }
        CP_COMMIT();
    };

    load_chunk(0, 0);
    load_chunk(1, 1);

    float acc[4][8][4];
#pragma unroll
    for (int i = 0; i < 4; i++)
#pragma unroll
        for (int j = 0; j < 8; j++)
#pragma unroll
            for (int r = 0; r < 4; r++) acc[i][j][r] = 0.f;

    const int arow = ((lane >> 3) & 1) * 8 + (lane & 7);
    const int acol = (lane >> 4) * 8;
    const int brow = ((lane >> 4) & 1) * 8 + (lane & 7);
    const int bcol = ((lane >> 3) & 1) * 8;

#pragma unroll 1
    for (int c = 0; c < NC; c++) {
        if (c + 1 < NC) CP_WAIT(1); else CP_WAIT(0);
        __syncthreads();
        const int sel = c & 1;
        const uint32_t bA = sb + WS_A(sel);
        const uint32_t bB = sb + WS_B(sel);
#pragma unroll
        for (int ks = 0; ks < 64; ks += 16) {
            uint32_t ah[4][4];
#pragma unroll
            for (int mf = 0; mf < 4; mf++) {
                const uint32_t ao = (uint32_t)((mf * 16 + arow) * LDR + (ks + acol) * 2);
                LDSM4(ah[mf][0], ah[mf][1], ah[mf][2], ah[mf][3], bA + ao);
            }
#pragma unroll
            for (int nq = 0; nq < 4; nq++) {
                const uint32_t bo = (uint32_t)((nbase + nq * 16 + brow) * LDR
                                               + (ks + bcol) * 2);
                uint32_t b[4];
                LDSM4(b[0], b[1], b[2], b[3], bB + bo);
#pragma unroll
                for (int mf = 0; mf < 4; mf++) {
                    MMA16816(acc[mf][nq * 2],     ah[mf], b[0], b[1]);
                    MMA16816(acc[mf][nq * 2 + 1], ah[mf], b[2], b[3]);
                }
            }
        }
        __syncthreads();
        if (c + 2 < NC) load_chunk(c + 2, sel);
    }

#pragma unroll
    for (int mf = 0; mf < 4; mf++)
#pragma unroll
        for (int rh = 0; rh < 2; rh++) {
            float s = 0.f, s2 = 0.f;
#pragma unroll
            for (int idx = 0; idx < 8; idx++) {
                const int c0 = nbase + idx * 8 + (lane & 3) * 2;
                float v0 = acc[mf][idx][rh * 2]     + sBias[c0];
                float v1 = acc[mf][idx][rh * 2 + 1] + sBias[c0 + 1];
                acc[mf][idx][rh * 2] = v0; acc[mf][idx][rh * 2 + 1] = v1;
                s += v0 + v1; s2 += v0 * v0 + v1 * v1;
            }
            s  += __shfl_xor_sync(0xffffffffu, s, 1);
            s  += __shfl_xor_sync(0xffffffffu, s, 2);
            s2 += __shfl_xor_sync(0xffffffffu, s2, 1);
            s2 += __shfl_xor_sync(0xffffffffu, s2, 2);
            if ((lane & 3) == 0) {
                const int row = mf * 16 + (lane >> 2) + rh * 8;
                atomicAdd(&sSum[row], s);
                atomicAdd(&sSum2[row], s2);
            }
        }
    __syncthreads();
    if (tid < 64) {
        const float mu = sSum[tid] * (1.f / 512.f);
        const float var = sSum2[tid] * (1.f / 512.f) - mu * mu;
        sMu[tid] = mu; sRs[tid] = rsqrtf(var + 1e-5f);
    }
    __syncthreads();

#pragma unroll
    for (int mf = 0; mf < 4; mf++)
#pragma unroll
        for (int rh = 0; rh < 2; rh++) {
            const int row = mf * 16 + (lane >> 2) + rh * 8;
            const float mu = sMu[row], rs = sRs[row];
            float zp[8];
            if (WRITE_Z) {
#pragma unroll
                for (int j = 0; j < 8; j++) zp[j] = 0.f;
            }
            const size_t rowg = (size_t)tile * 64 + row;
#pragma unroll
            for (int idx = 0; idx < 8; idx++) {
                const int c0 = nbase + idx * 8 + (lane & 3) * 2;
                float y0 = (acc[mf][idx][rh * 2]     - mu) * rs * sG[c0]     + sBe[c0];
                float y1 = (acc[mf][idx][rh * 2 + 1] - mu) * rs * sG[c0 + 1] + sBe[c0 + 1];
                y0 = y0 * (1.f / (1.f + __expf(-y0)));
                y1 = y1 * (1.f / (1.f + __expf(-y1)));
                if (WRITE_Z) {
                    const float* w0 = sW3 + c0 * 8;
#pragma unroll
                    for (int j = 0; j < 8; j++) {
                        zp[j] = fmaf(y0, w0[j], zp[j]);
                        zp[j] = fmaf(y1, w0[8 + j], zp[j]);
                    }
                } else {
                    *(uint32_t*)(O + rowg * 512 + c0) = pack_h2(y0, y1);
                }
            }
            if (WRITE_Z) {
#pragma unroll
                for (int j = 0; j < 8; j++) {
                    zp[j] += __shfl_xor_sync(0xffffffffu, zp[j], 1);
                    zp[j] += __shfl_xor_sync(0xffffffffu, zp[j], 2);
                }
                if ((lane & 3) == 0)
#pragma unroll
                    for (int j = 0; j < 8; j++)
                        atomicAdd(&sZ[row * 8 + j], zp[j]);
            }
        }

    if (WRITE_Z) {
        __syncthreads();
        if (tid < 64) {
            const size_t rowg = (size_t)tile * 64 + tid;
#pragma unroll
            for (int j = 0; j < 8; j++)
                z0out[rowg * 8 + j] = tanhf(sZ[tid * 8 + j] + __ldg(b3 + j));
        }
    }
}

// ============================================================================
// enc1 layer (K=64): 512 threads = 16 warps (2Mx8N), warp m32 x n64, single
// 64-K chunk (round-14 proven configuration).
// ============================================================================
__global__ __launch_bounds__(512, 1)
void enc1_mma_kernel(const __half* __restrict__ A,
                     const __half* __restrict__ W,
                     const float* __restrict__ bias,
                     const float* __restrict__ gamma,
                     const float* __restrict__ beta,
                     __half* __restrict__ O)
{
    extern __shared__ char smem[];
    const uint32_t sb = smem_u32(smem);
    const int tid = threadIdx.x, lane = tid & 31, w = tid >> 5;
    const int warpM = w >> 3, warpN = w & 7;
    const int nbase = warpN * 64;
    const int tile = blockIdx.x;

    float* sBias = (float*)(smem + WS_PAR);
    float* sG    = (float*)(smem + WS_PAR + 2048);
    float* sBe   = (float*)(smem + WS_PAR + 4096);
    float* sSum  = (float*)(smem + WS_RED);
    float* sSum2 = (float*)(smem + WS_RED + 256);
    float* sMu   = (float*)(smem + WS_RED + 512);
    float* sRs   = (float*)(smem + WS_RED + 768);

    sBias[tid] = bias[tid]; sG[tid] = gamma[tid]; sBe[tid] = beta[tid];
    if (tid < 64) { sSum[tid] = 0.f; sSum2[tid] = 0.f; }

    {
        const uint32_t bB = sb + WS_B(0);
#pragma unroll
        for (int i = tid; i < 4096; i += 512) {
            const int row = i >> 3, j = i & 7;
            cp16(bB + row * LDR + j * 16,
                 (const char*)W + ((size_t)row * 64) * 2 + j * 16);
        }
        {
            const int row = tid >> 3, j = tid & 7;
            cp16(sb + WS_A(0) + row * LDR + j * 16,
                 (const char*)A + (((size_t)tile * 64 + row) * 64) * 2 + j * 16);
        }
        CP_COMMIT();
    }

    float acc[2][8][4];
#pragma unroll
    for (int i = 0; i < 2; i++)
#pragma unroll
        for (int j = 0; j < 8; j++)
#pragma unroll
            for (int r = 0; r < 4; r++) acc[i][j][r] = 0.f;

    const int arow = ((lane >> 3) & 1) * 8 + (lane & 7);
    const int acol = (lane >> 4) * 8;
    const int brow = ((lane >> 4) & 1) * 8 + (lane & 7);
    const int bcol = ((lane >> 3) & 1) * 8;

    CP_WAIT(0);
    __syncthreads();
    {
        const uint32_t bA = sb + WS_A(0);
        const uint32_t bB = sb + WS_B(0);
#pragma unroll
        for (int ks = 0; ks < 64; ks += 16) {
            uint32_t ah[2][4];
#pragma unroll
            for (int mf = 0; mf < 2; mf++) {
                const uint32_t ao = (uint32_t)((warpM * 32 + mf * 16 + arow) * LDR
                                               + (ks + acol) * 2);
                LDSM4(ah[mf][0], ah[mf][1], ah[mf][2], ah[mf][3], bA + ao);
            }
#pragma unroll
            for (int nq = 0; nq < 4; nq++) {
                const uint32_t bo = (uint32_t)((nbase + nq * 16 + brow) * LDR
                                               + (ks + bcol) * 2);
                uint32_t b[4];
                LDSM4(b[0], b[1], b[2], b[3], bB + bo);
#pragma unroll
                for (int mf = 0; mf < 2; mf++) {
                    MMA16816(acc[mf][nq * 2],     ah[mf], b[0], b[1]);
                    MMA16816(acc[mf][nq * 2 + 1], ah[mf], b[2], b[3]);
                }
            }
        }
    }

#pragma unroll
    for (int mf = 0; mf < 2; mf++)
#pragma unroll
        for (int rh = 0; rh < 2; rh++) {
            float s = 0.f, s2 = 0.f;
#pragma unroll
            for (int idx = 0; idx < 8; idx++) {
                const int c0 = nbase + idx * 8 + (lane & 3) * 2;
                float v0 = acc[mf][idx][rh * 2]     + sBias[c0];
                float v1 = acc[mf][idx][rh * 2 + 1] + sBias[c0 + 1];
                acc[mf][idx][rh * 2] = v0; acc[mf][idx][rh * 2 + 1] = v1;
                s += v0 + v1; s2 += v0 * v0 + v1 * v1;
            }
            s  += __shfl_xor_sync(0xffffffffu, s, 1);
            s  += __shfl_xor_sync(0xffffffffu, s, 2);
            s2 += __shfl_xor_sync(0xffffffffu, s2, 1);
            s2 += __shfl_xor_sync(0xffffffffu, s2, 2);
            if ((lane & 3) == 0) {
                const int row = warpM * 32 + mf * 16 + (lane >> 2) + rh * 8;
                atomicAdd(&sSum[row], s);
                atomicAdd(&sSum2[row], s2);
            }
        }
    __syncthreads();
    if (tid < 64) {
        const float mu = sSum[tid] * (1.f / 512.f);
        const float var = sSum2[tid] * (1.f / 512.f) - mu * mu;
        sMu[tid] = mu; sRs[tid] = rsqrtf(var + 1e-5f);
    }
    __syncthreads();

#pragma unroll
    for (int mf = 0; mf < 2; mf++)
#pragma unroll
        for (int rh = 0; rh < 2; rh++) {
            const int row = warpM * 32 + mf * 16 + (lane >> 2) + rh * 8;
            const float mu = sMu[row], rs = sRs[row];
            const size_t rowg = (size_t)tile * 64 + row;
#pragma unroll
            for (int idx = 0; idx < 8; idx++) {
                const int c0 = nbase + idx * 8 + (lane & 3) * 2;
                float y0 = (acc[mf][idx][rh * 2]     - mu) * rs * sG[c0]     + sBe[c0];
                float y1 = (acc[mf][idx][rh * 2 + 1] - mu) * rs * sG[c0 + 1] + sBe[c0 + 1];
                y0 = y0 * (1.f / (1.f + __expf(-y0)));
                y1 = y1 * (1.f / (1.f + __expf(-y1)));
                *(uint32_t*)(O + rowg * 512 + c0) = pack_h2(y0, y1);
            }
        }
}

// ============================================================================
// DEC fused kernel (round-15 measured winner: 432us): dec2 GEMM + LN/SiLU ->
// h2 into dead stage-0 smem, W3 into dead stage-1, then n8-per-warp out MMA.
// ============================================================================
#define D_ST(s)  ((s) * 82944)
#define D_PAR    165888
#define D_RED    172032
#define SM_DEC   173056

__global__ __launch_bounds__(256, 1)
void dec_fused_kernel(const __half* __restrict__ A,
                      const __half* __restrict__ Wg,
                      const float* __restrict__ b2, const float* __restrict__ g2,
                      const float* __restrict__ be2,
                      const __half* __restrict__ W3h,
                      const float* __restrict__ b3,
                      float* __restrict__ out)
{
    extern __shared__ char smem[];
    const uint32_t sb = smem_u32(smem);
    const int tid = threadIdx.x, lane = tid & 31, w = tid >> 5;
    const int nbase = w * 64;
    const int tile = blockIdx.x;

    float* sB2  = (float*)(smem + D_PAR);
    float* sG2  = (float*)(smem + D_PAR + 2048);
    float* sBe2 = (float*)(smem + D_PAR + 4096);
    float* sSum  = (float*)(smem + D_RED);
    float* sSum2 = (float*)(smem + D_RED + 256);
    float* sMu   = (float*)(smem + D_RED + 512);
    float* sRs   = (float*)(smem + D_RED + 768);

    for (int i = tid; i < 512; i += 256) { sB2[i] = b2[i]; sG2[i] = g2[i]; sBe2[i] = be2[i]; }
    if (tid < 64) { sSum[tid] = 0.f; sSum2[tid] = 0.f; }

    auto load_chunk = [&](int c, int s) {
        const int kbase = c * 64;
        const uint32_t bB = sb + D_ST(s) + 9216;
#pragma unroll
        for (int i = tid; i < 4096; i += 256) {
            const int row = i >> 3, j = i & 7;
            cp16(bB + row * LDR + j * 16,
                 (const char*)Wg + ((size_t)row * 512 + kbase) * 2 + j * 16);
        }
#pragma unroll
        for (int i = tid; i < 512; i += 256) {
            const int row = i >> 3, j = i & 7;
            cp16(sb + D_ST(s) + row * LDR + j * 16,
                 (const char*)A + (((size_t)tile * 64 + row) * 512 + kbase) * 2 + j * 16);
        }
        CP_COMMIT();
    };
    load_chunk(0, 0);
    load_chunk(1, 1);

    float acc[4][8][4];
#pragma unroll
    for (int i = 0; i < 4; i++)
#pragma unroll
        for (int j = 0; j < 8; j++)
#pragma unroll
            for (int r = 0; r < 4; r++) acc[i][j][r] = 0.f;

    const int arow = ((lane >> 3) & 1) * 8 + (lane & 7);
    const int acol = (lane >> 4) * 8;
    const int brow = ((lane >> 4) & 1) * 8 + (lane & 7);
    const int bcol = ((lane >> 3) & 1) * 8;

#pragma unroll 1
    for (int c = 0; c < 8; c++) {
        if (c + 1 < 8) CP_WAIT(1); else CP_WAIT(0);
        __syncthreads();
        const int sel = c & 1;
        const uint32_t bA = sb + D_ST(sel);
        const uint32_t bB = sb + D_ST(sel) + 9216;
#pragma unroll
        for (int ks = 0; ks < 64; ks += 16) {
            uint32_t ah[4][4];
#pragma unroll
            for (int mf = 0; mf < 4; mf++) {
                const uint32_t ao = (uint32_t)((mf * 16 + arow) * LDR + (ks + acol) * 2);
                LDSM4(ah[mf][0], ah[mf][1], ah[mf][2], ah[mf][3], bA + ao);
            }
#pragma unroll
            for (int nq = 0; nq < 4; nq++) {
                const uint32_t bo = (uint32_t)((nbase + nq * 16 + brow) * LDR
                                               + (ks + bcol) * 2);
                uint32_t b[4];
                LDSM4(b[0], b[1], b[2], b[3], bB + bo);
#pragma unroll
                for (int mf = 0; mf < 4; mf++) {
                    MMA16816(acc[mf][nq * 2],     ah[mf], b[0], b[1]);
                    MMA16816(acc[mf][nq * 2 + 1], ah[mf], b[2], b[3]);
                }
            }
        }
        __syncthreads();
        if (c + 2 < 8) load_chunk(c + 2, sel);
    }

#pragma unroll
    for (int mf = 0; mf < 4; mf++)
#pragma unroll
        for (int rh = 0; rh < 2; rh++) {
            float s = 0.f, s2 = 0.f;
#pragma unroll
            for (int idx = 0; idx < 8; idx++) {
                const int c0 = nbase + idx * 8 + (lane & 3) * 2;
                float v0 = acc[mf][idx][rh * 2]     + sB2[c0];
                float v1 = acc[mf][idx][rh * 2 + 1] + sB2[c0 + 1];
                acc[mf][idx][rh * 2] = v0; acc[mf][idx][rh * 2 + 1] = v1;
                s += v0 + v1; s2 += v0 * v0 + v1 * v1;
            }
            s  += __shfl_xor_sync(0xffffffffu, s, 1);
            s  += __shfl_xor_sync(0xffffffffu, s, 2);
            s2 += __shfl_xor_sync(0xffffffffu, s2, 1);
            s2 += __shfl_xor_sync(0xffffffffu, s2, 2);
            if ((lane & 3) == 0) {
                const int row = mf * 16 + (lane >> 2) + rh * 8;
                atomicAdd(&sSum[row], s);
                atomicAdd(&sSum2[row], s2);
            }
        }
    {
        const uint32_t s1 = sb + D_ST(1);
#pragma unroll
        for (int i = tid; i < 4096; i += 256) {
            const int ck = i >> 9, rem = i & 511;
            const int row = rem >> 3, j = rem & 7;
            cp16(s1 + ck * 9216 + row * LDR + j * 16,
                 (const char*)W3h + ((size_t)row * 512 + ck * 64) * 2 + j * 16);
        }
        CP_COMMIT();
    }
    __syncthreads();
    if (tid < 64) {
        const float mu = sSum[tid] * (1.f / 512.f);
        const float var = sSum2[tid] * (1.f / 512.f) - mu * mu;
        sMu[tid] = mu; sRs[tid] = rsqrtf(var + 1e-5f);
    }
    __syncthreads();

#pragma unroll
    for (int mf = 0; mf < 4; mf++)
#pragma unroll
        for (int rh = 0; rh < 2; rh++) {
            const int row = mf * 16 + (lane >> 2) + rh * 8;
            const float mu = sMu[row], rs = sRs[row];
#pragma unroll
            for (int idx = 0; idx < 8; idx++) {
                const int cl = idx * 8 + (lane & 3) * 2;
                const int c0 = nbase + cl;
                float y0 = (acc[mf][idx][rh * 2]     - mu) * rs * sG2[c0]     + sBe2[c0];
                float y1 = (acc[mf][idx][rh * 2 + 1] - mu) * rs * sG2[c0 + 1] + sBe2[c0 + 1];
                y0 = y0 * (1.f / (1.f + __expf(-y0)));
                y1 = y1 * (1.f / (1.f + __expf(-y1)));
                *(uint32_t*)(smem + D_ST(0) + w * 9216 + row * LDR + cl * 2)
                    = pack_h2(y0, y1);
            }
        }
    CP_WAIT(0);
    __syncthreads();

    float acc2[4][4];
#pragma unroll
    for (int i = 0; i < 4; i++)
#pragma unroll
        for (int r = 0; r < 4; r++) acc2[i][r] = 0.f;

    const int l16 = lane & 15;
#pragma unroll 1
    for (int ck = 0; ck < 8; ck++) {
        const uint32_t bA = sb + D_ST(0) + ck * 9216;
        const uint32_t s1 = sb + D_ST(1) + ck * 9216;
#pragma unroll
        for (int ks = 0; ks < 64; ks += 16) {
            uint32_t ah[4][4];
#pragma unroll
            for (int mf = 0; mf < 4; mf++) {
                const uint32_t ao = (uint32_t)((mf * 16 + arow) * LDR + (ks + acol) * 2);
                LDSM4(ah[mf][0], ah[mf][1], ah[mf][2], ah[mf][3], bA + ao);
            }
            uint32_t b0, b1;
            const uint32_t bo = (uint32_t)((w * 8 + (l16 & 7)) * LDR + ks * 2
                                           + ((l16 >> 3) << 4));
            LDSM2(b0, b1, s1 + bo);
#pragma unroll
            for (int mf = 0; mf < 4; mf++)
                MMA16816(acc2[mf], ah[mf], b0, b1);
        }
    }

#pragma unroll
    for (int mf = 0; mf < 4; mf++)
#pragma unroll
        for (int rh = 0; rh < 2; rh++) {
            const int row = mf * 16 + (lane >> 2) + rh * 8;
            const int c0 = w * 8 + (lane & 3) * 2;
            float2 o;
            o.x = acc2[mf][rh * 2]     + __ldg(b3 + c0);
            o.y = acc2[mf][rh * 2 + 1] + __ldg(b3 + c0 + 1);
            *(float2*)(out + ((size_t)tile * 64 + row) * 64 + c0) = o;
        }
}

// ============================================================================
// integrator + FUSED dec layer 1 (round-14 proven)
// ============================================================================
__global__ __launch_bounds__(256, 2)
void integrate_dec1_kernel(const float* __restrict__ z0,
                           const float* __restrict__ dtv,
                           const float* __restrict__ Xi,
                           const float* __restrict__ W1,
                           const float* __restrict__ b1,
                           const float* __restrict__ g1,
                           const float* __restrict__ be1,
                           __half* __restrict__ O)
{
    __shared__ float Xis[NTH * LDIM];
    __shared__ float sW[8 * 512];
    __shared__ float sB1[512], sG1[512], sBe1[512];
    __shared__ float sZr[256 * 9];

    const int tid = threadIdx.x, lane = tid & 31, w = tid >> 5;
    for (int i = tid; i < NTH * LDIM; i += 256) Xis[i] = Xi[i];
    for (int i = tid; i < 8 * 512; i += 256) sW[i] = W1[i];
    for (int i = tid; i < 512; i += 256) { sB1[i] = b1[i]; sG1[i] = g1[i]; sBe1[i] = be1[i]; }
    __syncthreads();

    const size_t row = (size_t)blockIdx.x * 256 + tid;
    float z[8];
    *(float4*)&z[0] = *(const float4*)(z0 + row * 8);
    *(float4*)&z[4] = *(const float4*)(z0 + row * 8 + 4);
    const float dt = dtv[row] * (1.f / (float)NSTEPS);

#pragma unroll 1
    for (int s = 0; s < NSTEPS; s++) {
        float zd[8];
#pragma unroll
        for (int j = 0; j < 8; j++) zd[j] = Xis[j];
#pragma unroll
        for (int i = 0; i < 8; i++) {
            const float t = z[i];
#pragma unroll
            for (int j = 0; j < 8; j++)
                zd[j] = fmaf(t, Xis[(1 + i) * 8 + j], zd[j]);
        }
        int idx = 9;
#pragma unroll
        for (int i = 0; i < 8; i++)
#pragma unroll
            for (int k = i; k < 8; k++) {
                const float q = z[i] * z[k];
#pragma unroll
                for (int j = 0; j < 8; j++)
                    zd[j] = fmaf(q, Xis[idx * 8 + j], zd[j]);
                idx++;
            }
#pragma unroll
        for (int j = 0; j < 8; j++) z[j] = fmaf(zd[j], dt, z[j]);
    }
#pragma unroll
    for (int j = 0; j < 8; j++) sZr[tid * 9 + j] = z[j];
    __syncthreads();

    const size_t rowbase = (size_t)blockIdx.x * 256;
#pragma unroll 1
    for (int it = 0; it < 32; it++) {
        const int lr = it * 8 + w;
        float zz[8];
#pragma unroll
        for (int k = 0; k < 8; k++) zz[k] = sZr[lr * 9 + k];
        float a0[8], a1[8];
#pragma unroll
        for (int j = 0; j < 8; j++) {
            const int c0 = j * 64 + lane * 2;
            float x0 = sB1[c0], x1 = sB1[c0 + 1];
#pragma unroll
            for (int k = 0; k < 8; k++) {
                x0 = fmaf(zz[k], sW[k * 512 + c0],     x0);
                x1 = fmaf(zz[k], sW[k * 512 + c0 + 1], x1);
            }
            a0[j] = x0; a1[j] = x1;
        }
        float s = 0.f, s2 = 0.f;
#pragma unroll
        for (int j = 0; j < 8; j++) {
            s += a0[j] + a1[j]; s2 += a0[j] * a0[j] + a1[j] * a1[j];
        }
#pragma unroll
        for (int o = 16; o; o >>= 1) {
            s  += __shfl_xor_sync(0xffffffffu, s, o);
            s2 += __shfl_xor_sync(0xffffffffu, s2, o);
        }
        const float mu = s * (1.f / 512.f);
        const float rs = rsqrtf(s2 * (1.f / 512.f) - mu * mu + 1e-5f);
        __half* orow = O + (rowbase + lr) * 512;
#pragma unroll
        for (int j = 0; j < 8; j++) {
            const int c0 = j * 64 + lane * 2;
            float y0 = (a0[j] - mu) * rs * sG1[c0]     + sBe1[c0];
            float y1 = (a1[j] - mu) * rs * sG1[c0 + 1] + sBe1[c0 + 1];
            y0 = y0 * (1.f / (1.f + __expf(-y0)));
            y1 = y1 * (1.f / (1.f + __expf(-y1)));
            *(uint32_t*)(orow + c0) = pack_h2(y0, y1);
        }
    }
}

// ============================================================================
extern "C" void kernel_launch(void* const* d_in, const int* in_sizes, int n_in,
                              void* d_out, int out_size)
{
    (void)in_sizes; (void)n_in; (void)out_size;
    const float* x0   = (const float*)d_in[0];
    const float* dtn  = (const float*)d_in[1];
    const float* eW1  = (const float*)d_in[4];
    const float* eb1  = (const float*)d_in[5];
    const float* eg1  = (const float*)d_in[6];
    const float* ebe1 = (const float*)d_in[7];
    const float* eW2  = (const float*)d_in[8];
    const float* eb2  = (const float*)d_in[9];
    const float* eg2  = (const float*)d_in[10];
    const float* ebe2 = (const float*)d_in[11];
    const float* eW3  = (const float*)d_in[12];
    const float* eb3  = (const float*)d_in[13];
    const float* dW1  = (const float*)d_in[14];
    const float* db1  = (const float*)d_in[15];
    const float* dg1  = (const float*)d_in[16];
    const float* dbe1 = (const float*)d_in[17];
    const float* dW2  = (const float*)d_in[18];
    const float* db2  = (const float*)d_in[19];
    const float* dg2  = (const float*)d_in[20];
    const float* dbe2 = (const float*)d_in[21];
    const float* dW3  = (const float*)d_in[22];
    const float* db3  = (const float*)d_in[23];
    const float* Xi   = (const float*)d_in[24];
    float* out = (float*)d_out;

    __half *hA, *xh, *w1, *w2, *d2, *d3;
    float* z0;
    cudaGetSymbolAddress((void**)&hA, g_hA);
    cudaGetSymbolAddress((void**)&xh, g_x);
    cudaGetSymbolAddress((void**)&z0, g_z0);
    cudaGetSymbolAddress((void**)&w1, g_w1);
    cudaGetSymbolAddress((void**)&w2, g_w2);
    cudaGetSymbolAddress((void**)&d2, g_d2);
    cudaGetSymbolAddress((void**)&d3, g_d3);

    cudaFuncSetAttribute(enc1_mma_kernel,
        cudaFuncAttributeMaxDynamicSharedMemorySize, SM_WIDE);
    cudaFuncSetAttribute(wide_mma_k512<true>,
        cudaFuncAttributeMaxDynamicSharedMemorySize, SM_WIDE);
    cudaFuncSetAttribute(dec_fused_kernel,
        cudaFuncAttributeMaxDynamicSharedMemorySize, SM_DEC);

    prep_all_kernel<<<(SEG3 + 255) / 256, 256>>>(eW1, eW2, dW2, dW3,
                                                 w1, w2, d2, d3);
    prep_x_kernel<<<(BATCH * 64) / 256, 256>>>(x0, xh);

    const int nwide = BATCH / 64;    // 2048

    // encoder layer 1
    enc1_mma_kernel<<<nwide, 512, SM_WIDE>>>(xh, w1, eb1, eg1, ebe1, hA);
    // encoder layer 2 + fused layer 3 -> z0
    wide_mma_k512<true><<<nwide, 256, SM_WIDE>>>(
        hA, w2, eb2, eg2, ebe2, nullptr, eW3, eb3, z0);
    // integrator + fused decoder layer 1 -> hA
    integrate_dec1_kernel<<<BATCH / 256, 256>>>(z0, dtn, Xi, dW1, db1, dg1, dbe1, hA);
    // decoder (dec2 + dec3 fused) -> out
    dec_fused_kernel<<<nwide, 256, SM_DEC>>>(
        hA, d2, db2, dg2, dbe2, d3, db3, out);
}